// round 2
// baseline (speedup 1.0000x reference)
#include <cuda_runtime.h>

// Problem constants (fixed shapes)
#define NN 10000      // nodes
#define NE 320000     // edges
#define DD 128        // feature dim
#define HH 512        // hidden dim

// Scratch: aggregated messages per node (5.12 MB, static device array — no allocs)
__device__ float g_agg[NN * DD];

// ---------------------------------------------------------------------------
// Zero the aggregation buffer
// ---------------------------------------------------------------------------
__global__ void zero_agg_kernel() {
    int i = blockIdx.x * blockDim.x + threadIdx.x;
    if (i < NN * DD) g_agg[i] = 0.0f;
}

// ---------------------------------------------------------------------------
// Edge MLP:  out_e = relu([x[s], x[r], ea] @ W1 + b1) @ W2 + b2
// Also scatter-adds out_e into g_agg[receiver].
// 64 edges per block, 256 threads, thread tile 4 rows x 8 cols.
// smem: As[64][384] (96KB) + Wt[32][128] (16KB) + Hs[64][128] (32KB) = 144KB
// ---------------------------------------------------------------------------
__global__ __launch_bounds__(256, 1)
void edge_mlp_kernel(const float* __restrict__ x,
                     const int* __restrict__ eidx,   // int32! (JAX x64 disabled)
                     const float* __restrict__ ea,
                     const float* __restrict__ W1, const float* __restrict__ b1,
                     const float* __restrict__ W2, const float* __restrict__ b2,
                     float* __restrict__ out_e)
{
    const int K = 384;
    extern __shared__ float sm[];
    float* As = sm;                 // 64 * 384
    float* Wt = As + 64 * K;        // 32 * 128
    float* Hs = Wt + 32 * 128;      // 64 * 128
    __shared__ int s_send[64];
    __shared__ int s_recv[64];

    const int tid = threadIdx.x;
    const int tx = tid & 15;        // 0..15 -> 8 output cols each
    const int ty = tid >> 4;        // 0..15 -> 4 rows each
    const int e0 = blockIdx.x * 64;

    if (tid < 64) {
        int s = eidx[e0 + tid];
        int r = eidx[NE + e0 + tid];
        s_send[tid] = (s < 0) ? 0 : (s >= NN ? NN - 1 : s);
        s_recv[tid] = (r < 0) ? 0 : (r >= NN ? NN - 1 : r);
    }
    __syncthreads();

    // Gather A tile: [x[s] | x[r] | ea[e]]  (96 float4 per row)
    for (int idx = tid; idx < 64 * 96; idx += 256) {
        int row = idx / 96;
        int c4  = idx - row * 96;
        float4 v;
        if (c4 < 32)       v = ((const float4*)(x  + (size_t)s_send[row] * DD))[c4];
        else if (c4 < 64)  v = ((const float4*)(x  + (size_t)s_recv[row] * DD))[c4 - 32];
        else               v = ((const float4*)(ea + (size_t)(e0 + row)  * DD))[c4 - 64];
        ((float4*)(As + row * K))[c4] = v;
    }
    __syncthreads();

    float oacc[4][8];
    #pragma unroll
    for (int r = 0; r < 4; r++)
        #pragma unroll
        for (int c = 0; c < 8; c++) oacc[r][c] = 0.0f;

    // Loop over 4 hidden chunks of 128
    #pragma unroll 1
    for (int nc = 0; nc < 4; nc++) {
        float hacc[4][8];
        #pragma unroll
        for (int r = 0; r < 4; r++)
            #pragma unroll
            for (int c = 0; c < 8; c++) hacc[r][c] = 0.0f;

        // ---- GEMM1: A[64x384] @ W1[:, nc*128 : nc*128+128] ----
        #pragma unroll 1
        for (int k0 = 0; k0 < K; k0 += 32) {
            #pragma unroll
            for (int l = tid; l < 1024; l += 256) {
                int kk = l >> 5;
                int c4 = l & 31;
                ((float4*)(Wt + kk * 128))[c4] =
                    ((const float4*)(W1 + (size_t)(k0 + kk) * HH + nc * 128))[c4];
            }
            __syncthreads();
            #pragma unroll
            for (int k = 0; k < 32; k++) {
                float a[4];
                #pragma unroll
                for (int r = 0; r < 4; r++) a[r] = As[(ty * 4 + r) * K + k0 + k];
                float4 w0 = ((const float4*)(Wt + k * 128))[tx * 2];
                float4 w1 = ((const float4*)(Wt + k * 128))[tx * 2 + 1];
                float w[8] = {w0.x, w0.y, w0.z, w0.w, w1.x, w1.y, w1.z, w1.w};
                #pragma unroll
                for (int r = 0; r < 4; r++)
                    #pragma unroll
                    for (int c = 0; c < 8; c++)
                        hacc[r][c] = fmaf(a[r], w[c], hacc[r][c]);
            }
            __syncthreads();
        }

        // bias + relu -> Hs
        #pragma unroll
        for (int c = 0; c < 8; c++) {
            float bias = b1[nc * 128 + tx * 8 + c];
            #pragma unroll
            for (int r = 0; r < 4; r++) {
                float v = hacc[r][c] + bias;
                Hs[(ty * 4 + r) * 128 + tx * 8 + c] = v > 0.0f ? v : 0.0f;
            }
        }
        __syncthreads();

        // ---- GEMM2: oacc += Hs[64x128] @ W2[nc*128 : nc*128+128, :] ----
        #pragma unroll 1
        for (int k0 = 0; k0 < 128; k0 += 32) {
            #pragma unroll
            for (int l = tid; l < 1024; l += 256) {
                int kk = l >> 5;
                int c4 = l & 31;
                ((float4*)(Wt + kk * 128))[c4] =
                    ((const float4*)(W2 + (size_t)(nc * 128 + k0 + kk) * DD))[c4];
            }
            __syncthreads();
            #pragma unroll
            for (int k = 0; k < 32; k++) {
                float a[4];
                #pragma unroll
                for (int r = 0; r < 4; r++) a[r] = Hs[(ty * 4 + r) * 128 + k0 + k];
                float4 w0 = ((const float4*)(Wt + k * 128))[tx * 2];
                float4 w1 = ((const float4*)(Wt + k * 128))[tx * 2 + 1];
                float w[8] = {w0.x, w0.y, w0.z, w0.w, w1.x, w1.y, w1.z, w1.w};
                #pragma unroll
                for (int r = 0; r < 4; r++)
                    #pragma unroll
                    for (int c = 0; c < 8; c++)
                        oacc[r][c] = fmaf(a[r], w[c], oacc[r][c]);
            }
            __syncthreads();
        }
    }

    // Epilogue: + b2, write edge output, scatter-add into g_agg[receiver]
    float b2v[8];
    #pragma unroll
    for (int c = 0; c < 8; c++) b2v[c] = b2[tx * 8 + c];

    #pragma unroll
    for (int r = 0; r < 4; r++) {
        int row = ty * 4 + r;
        size_t e = (size_t)(e0 + row);
        float v[8];
        #pragma unroll
        for (int c = 0; c < 8; c++) v[c] = oacc[r][c] + b2v[c];
        float4* dst = (float4*)(out_e + e * DD + tx * 8);
        dst[0] = make_float4(v[0], v[1], v[2], v[3]);
        dst[1] = make_float4(v[4], v[5], v[6], v[7]);
        float* ag = g_agg + (size_t)s_recv[row] * DD + tx * 8;
        #pragma unroll
        for (int c = 0; c < 8; c++) atomicAdd(ag + c, v[c]);
    }
}

// ---------------------------------------------------------------------------
// Node MLP:  out_n = relu([x, agg] @ Wn1 + bn1) @ Wn2 + bn2
// 64 nodes per block. smem: As[64][256] (64KB) + Wt (16KB) + Hs (32KB) = 112KB
// ---------------------------------------------------------------------------
__global__ __launch_bounds__(256, 1)
void node_mlp_kernel(const float* __restrict__ x,
                     const float* __restrict__ W1, const float* __restrict__ b1,
                     const float* __restrict__ W2, const float* __restrict__ b2,
                     float* __restrict__ out_n)
{
    const int K = 256;
    extern __shared__ float sm[];
    float* As = sm;                 // 64 * 256
    float* Wt = As + 64 * K;        // 32 * 128
    float* Hs = Wt + 32 * 128;      // 64 * 128

    const int tid = threadIdx.x;
    const int tx = tid & 15;
    const int ty = tid >> 4;
    const int n0 = blockIdx.x * 64;

    // Gather A tile: [x[n] | agg[n]]  (64 float4 per row)
    for (int idx = tid; idx < 64 * 64; idx += 256) {
        int row = idx >> 6;
        int c4  = idx & 63;
        int n = n0 + row;
        int ns = n < NN ? n : 0;
        float4 v;
        if (c4 < 32) v = ((const float4*)(x     + (size_t)ns * DD))[c4];
        else         v = ((const float4*)(g_agg + (size_t)ns * DD))[c4 - 32];
        ((float4*)(As + row * K))[c4] = v;
    }
    __syncthreads();

    float oacc[4][8];
    #pragma unroll
    for (int r = 0; r < 4; r++)
        #pragma unroll
        for (int c = 0; c < 8; c++) oacc[r][c] = 0.0f;

    #pragma unroll 1
    for (int nc = 0; nc < 4; nc++) {
        float hacc[4][8];
        #pragma unroll
        for (int r = 0; r < 4; r++)
            #pragma unroll
            for (int c = 0; c < 8; c++) hacc[r][c] = 0.0f;

        #pragma unroll 1
        for (int k0 = 0; k0 < K; k0 += 32) {
            #pragma unroll
            for (int l = tid; l < 1024; l += 256) {
                int kk = l >> 5;
                int c4 = l & 31;
                ((float4*)(Wt + kk * 128))[c4] =
                    ((const float4*)(W1 + (size_t)(k0 + kk) * HH + nc * 128))[c4];
            }
            __syncthreads();
            #pragma unroll
            for (int k = 0; k < 32; k++) {
                float a[4];
                #pragma unroll
                for (int r = 0; r < 4; r++) a[r] = As[(ty * 4 + r) * K + k0 + k];
                float4 w0 = ((const float4*)(Wt + k * 128))[tx * 2];
                float4 w1 = ((const float4*)(Wt + k * 128))[tx * 2 + 1];
                float w[8] = {w0.x, w0.y, w0.z, w0.w, w1.x, w1.y, w1.z, w1.w};
                #pragma unroll
                for (int r = 0; r < 4; r++)
                    #pragma unroll
                    for (int c = 0; c < 8; c++)
                        hacc[r][c] = fmaf(a[r], w[c], hacc[r][c]);
            }
            __syncthreads();
        }

        #pragma unroll
        for (int c = 0; c < 8; c++) {
            float bias = b1[nc * 128 + tx * 8 + c];
            #pragma unroll
            for (int r = 0; r < 4; r++) {
                float v = hacc[r][c] + bias;
                Hs[(ty * 4 + r) * 128 + tx * 8 + c] = v > 0.0f ? v : 0.0f;
            }
        }
        __syncthreads();

        #pragma unroll 1
        for (int k0 = 0; k0 < 128; k0 += 32) {
            #pragma unroll
            for (int l = tid; l < 1024; l += 256) {
                int kk = l >> 5;
                int c4 = l & 31;
                ((float4*)(Wt + kk * 128))[c4] =
                    ((const float4*)(W2 + (size_t)(nc * 128 + k0 + kk) * DD))[c4];
            }
            __syncthreads();
            #pragma unroll
            for (int k = 0; k < 32; k++) {
                float a[4];
                #pragma unroll
                for (int r = 0; r < 4; r++) a[r] = Hs[(ty * 4 + r) * 128 + k0 + k];
                float4 w0 = ((const float4*)(Wt + k * 128))[tx * 2];
                float4 w1 = ((const float4*)(Wt + k * 128))[tx * 2 + 1];
                float w[8] = {w0.x, w0.y, w0.z, w0.w, w1.x, w1.y, w1.z, w1.w};
                #pragma unroll
                for (int r = 0; r < 4; r++)
                    #pragma unroll
                    for (int c = 0; c < 8; c++)
                        oacc[r][c] = fmaf(a[r], w[c], oacc[r][c]);
            }
            __syncthreads();
        }
    }

    float b2v[8];
    #pragma unroll
    for (int c = 0; c < 8; c++) b2v[c] = b2[tx * 8 + c];

    #pragma unroll
    for (int r = 0; r < 4; r++) {
        int row = ty * 4 + r;
        int n = n0 + row;
        if (n < NN) {
            float v[8];
            #pragma unroll
            for (int c = 0; c < 8; c++) v[c] = oacc[r][c] + b2v[c];
            float4* dst = (float4*)(out_n + (size_t)n * DD + tx * 8);
            dst[0] = make_float4(v[0], v[1], v[2], v[3]);
            dst[1] = make_float4(v[4], v[5], v[6], v[7]);
        }
    }
}

// ---------------------------------------------------------------------------
// Launch
// ---------------------------------------------------------------------------
extern "C" void kernel_launch(void* const* d_in, const int* in_sizes, int n_in,
                              void* d_out, int out_size)
{
    const float* x   = (const float*)d_in[0];
    const int*   ei  = (const int*)d_in[1];     // int32 (JAX default, x64 disabled)
    const float* ea  = (const float*)d_in[2];
    const float* We1 = (const float*)d_in[3];
    const float* be1 = (const float*)d_in[4];
    const float* We2 = (const float*)d_in[5];
    const float* be2 = (const float*)d_in[6];
    const float* Wn1 = (const float*)d_in[7];
    const float* bn1 = (const float*)d_in[8];
    const float* Wn2 = (const float*)d_in[9];
    const float* bn2 = (const float*)d_in[10];

    float* out_nodes = (float*)d_out;                       // [NN, DD] first
    float* out_edges = out_nodes + (size_t)NN * DD;         // [NE, DD] second

    const int edge_smem = (64 * 384 + 32 * 128 + 64 * 128) * (int)sizeof(float); // 147456
    const int node_smem = (64 * 256 + 32 * 128 + 64 * 128) * (int)sizeof(float); // 114688

    cudaFuncSetAttribute(edge_mlp_kernel,
                         cudaFuncAttributeMaxDynamicSharedMemorySize, edge_smem);
    cudaFuncSetAttribute(node_mlp_kernel,
                         cudaFuncAttributeMaxDynamicSharedMemorySize, node_smem);

    zero_agg_kernel<<<(NN * DD + 255) / 256, 256>>>();
    edge_mlp_kernel<<<NE / 64, 256, edge_smem>>>(x, ei, ea, We1, be1, We2, be2, out_edges);
    node_mlp_kernel<<<(NN + 63) / 64, 256, node_smem>>>(x, Wn1, bn1, Wn2, bn2, out_nodes);
}

// round 5
// speedup vs baseline: 1.4443x; 1.4443x over previous
#include <cuda_runtime.h>
#include <mma.h>
#include <cstdint>

using namespace nvcuda;

#define NN 10000
#define NE 320000
#define DD 128
#define HH 512

// ---------------- static device scratch ----------------
__device__ float g_agg[NN * DD];

// ---------------- helpers ----------------
__device__ __forceinline__ uint32_t smem_u32(const void* p) {
    uint32_t a;
    asm("{ .reg .u64 t; cvta.to.shared.u64 t, %1; cvt.u32.u64 %0, t; }" : "=r"(a) : "l"(p));
    return a;
}
__device__ __forceinline__ void cpa16(float* s, const float* g) {
    asm volatile("cp.async.cg.shared.global [%0], [%1], 16;"
                 :: "r"(smem_u32(s)), "l"(g) : "memory");
}
__device__ __forceinline__ void cp_commit() {
    asm volatile("cp.async.commit_group;" ::: "memory");
}
template<int N> __device__ __forceinline__ void cp_wait() {
    asm volatile("cp.async.wait_group %0;" :: "n"(N) : "memory");
}

using FragA = wmma::fragment<wmma::matrix_a, 16, 16, 8, wmma::precision::tf32, wmma::row_major>;
using FragB = wmma::fragment<wmma::matrix_b, 16, 16, 8, wmma::precision::tf32, wmma::row_major>;
using FragC = wmma::fragment<wmma::accumulator, 16, 16, 8, float>;

// One 32-wide K-chunk of MMA: acc[2][4] (warp tile 32x64) += A[128x32] @ B[32x128]
__device__ __forceinline__ void mma_tile(const float* __restrict__ A, int lda,
                                         const float* __restrict__ B, int ldb,
                                         FragC (&acc)[2][4], int m0, int n0)
{
    #pragma unroll
    for (int s = 0; s < 4; s++) {
        FragA af[2];
        FragB bf[4];
        #pragma unroll
        for (int i = 0; i < 2; i++) {
            wmma::load_matrix_sync(af[i], A + (m0 + i * 16) * lda + s * 8, lda);
            #pragma unroll
            for (int t = 0; t < af[i].num_elements; t++)
                af[i].x[t] = wmma::__float_to_tf32(af[i].x[t]);
        }
        #pragma unroll
        for (int j = 0; j < 4; j++) {
            wmma::load_matrix_sync(bf[j], B + (s * 8) * ldb + n0 + j * 16, ldb);
            #pragma unroll
            for (int t = 0; t < bf[j].num_elements; t++)
                bf[j].x[t] = wmma::__float_to_tf32(bf[j].x[t]);
        }
        #pragma unroll
        for (int i = 0; i < 2; i++)
            #pragma unroll
            for (int j = 0; j < 4; j++)
                wmma::mma_sync(acc[i][j], af[i], bf[j], acc[i][j]);
    }
}

// ---------------- small kernels ----------------
__global__ void zero_agg_kernel() {
    int i = blockIdx.x * blockDim.x + threadIdx.x;
    if (i < NN * DD) g_agg[i] = 0.0f;
}

// ---------------- smem layout (floats) ----------------
// As:   2 x [128][40]   @ 0      (10240 f)
// Ws:   2 x [32][136]   @ 10240  (8704 f)
// Hs:   [128][136]      @ 18944  (17408 f)
// b1s:  [512]           @ 36352
// b2s:  [128]           @ 36864
// idx:  [256] int       @ 36992
#define OFF_AS0 0
#define OFF_AS1 5120
#define OFF_WS0 10240
#define OFF_WS1 14592
#define OFF_HS  18944
#define OFF_B1  36352
#define OFF_B2  36864
#define OFF_IDX 36992
#define SMEM_FLOATS 37248
#define SMEM_BYTES (SMEM_FLOATS * 4)

// ---------------- edge MLP kernel ----------------
__global__ __launch_bounds__(256, 1)
void edge_wmma_kernel(const float* __restrict__ x, const int* __restrict__ eidx,
                      const float* __restrict__ ea,
                      const float* __restrict__ W1, const float* __restrict__ b1,
                      const float* __restrict__ W2, const float* __restrict__ b2,
                      float* __restrict__ out_e)
{
    extern __shared__ float sm[];
    float* As[2] = { sm + OFF_AS0, sm + OFF_AS1 };
    float* Ws[2] = { sm + OFF_WS0, sm + OFF_WS1 };
    float* Hs    = sm + OFF_HS;
    float* b1s   = sm + OFF_B1;
    float* b2s   = sm + OFF_B2;
    int*   ssend = (int*)(sm + OFF_IDX);
    int*   srecv = ssend + 128;

    const int tid = threadIdx.x;
    const int w   = tid >> 5;
    const int m0  = (w >> 1) * 32;   // warp row offset (4 m-warps)
    const int n0  = (w & 1) * 64;    // warp col offset (2 n-warps)
    const int e0  = blockIdx.x * 128;

    if (tid < 128) {
        int s = eidx[e0 + tid];
        ssend[tid] = min(max(s, 0), NN - 1);
    } else {
        int r = eidx[NE + e0 + tid - 128];
        srecv[tid - 128] = min(max(r, 0), NN - 1);
    }
    for (int i = tid; i < 512; i += 256) b1s[i] = b1[i];
    if (tid < 128) b2s[tid] = b2[tid];
    __syncthreads();

    // A-chunk gather loader: chunk kc in [0,12), 32 cols each
    auto loadA = [&](int buf, int kc) {
        const int koff = (kc & 3) * 32;
        #pragma unroll
        for (int i = tid; i < 1024; i += 256) {
            int row = i >> 3, seg = i & 7;
            const float* src;
            if (kc < 4)      src = x  + (size_t)ssend[row] * DD + koff;
            else if (kc < 8) src = x  + (size_t)srecv[row] * DD + koff;
            else             src = ea + (size_t)(e0 + row) * DD + koff;
            cpa16(As[buf] + row * 40 + seg * 4, src + seg * 4);
        }
    };
    // W1 chunk: rows kc*32..+32 of [384,512], cols nc*128..+128
    auto loadW1 = [&](int buf, int kc, int nc) {
        #pragma unroll
        for (int i = tid; i < 1024; i += 256) {
            int row = i >> 5, seg = i & 31;
            cpa16(Ws[buf] + row * 136 + seg * 4,
                  W1 + (size_t)(kc * 32 + row) * HH + nc * 128 + seg * 4);
        }
    };
    // W2 chunk: rows nc*128 + kc*32 ..+32 of [512,128], all 128 cols
    auto loadW2 = [&](int buf, int kc, int nc) {
        #pragma unroll
        for (int i = tid; i < 1024; i += 256) {
            int row = i >> 5, seg = i & 31;
            cpa16(Ws[buf] + row * 136 + seg * 4,
                  W2 + (size_t)(nc * 128 + kc * 32 + row) * DD + seg * 4);
        }
    };

    FragC acc2[2][4];
    #pragma unroll
    for (int i = 0; i < 2; i++)
        #pragma unroll
        for (int j = 0; j < 4; j++) wmma::fill_fragment(acc2[i][j], 0.0f);

    for (int nc = 0; nc < 4; nc++) {
        FragC acc1[2][4];
        #pragma unroll
        for (int i = 0; i < 2; i++)
            #pragma unroll
            for (int j = 0; j < 4; j++) wmma::fill_fragment(acc1[i][j], 0.0f);

        // ---- GEMM1: K = 384 (12 chunks), double-buffered ----
        loadA(0, 0); loadW1(0, 0, nc); cp_commit();
        for (int kc = 0; kc < 12; kc++) {
            int cur = kc & 1;
            if (kc < 11) {
                loadA(cur ^ 1, kc + 1); loadW1(cur ^ 1, kc + 1, nc); cp_commit();
                cp_wait<1>();
            } else {
                cp_wait<0>();
            }
            __syncthreads();
            mma_tile(As[cur], 40, Ws[cur], 136, acc1, m0, n0);
            __syncthreads();
        }

        // ---- acc1 -> Hs, bias + relu ----
        #pragma unroll
        for (int i = 0; i < 2; i++)
            #pragma unroll
            for (int j = 0; j < 4; j++)
                wmma::store_matrix_sync(Hs + (m0 + i * 16) * 136 + n0 + j * 16,
                                        acc1[i][j], 136, wmma::mem_row_major);
        __syncthreads();
        for (int idx = tid; idx < 16384; idx += 256) {
            int r = idx >> 7, c = idx & 127;
            float v = Hs[r * 136 + c] + b1s[nc * 128 + c];
            Hs[r * 136 + c] = v > 0.0f ? v : 0.0f;
        }
        __syncthreads();

        // ---- GEMM2: K = 128 (4 chunks of W2), A = Hs resident ----
        loadW2(0, 0, nc); cp_commit();
        for (int kc = 0; kc < 4; kc++) {
            int cur = kc & 1;
            if (kc < 3) {
                loadW2(cur ^ 1, kc + 1, nc); cp_commit();
                cp_wait<1>();
            } else {
                cp_wait<0>();
            }
            __syncthreads();
            mma_tile(Hs + kc * 32, 136, Ws[cur], 136, acc2, m0, n0);
            __syncthreads();
        }
    }

    // ---- epilogue: acc2 -> Hs, + b2, write out + scatter atomics ----
    #pragma unroll
    for (int i = 0; i < 2; i++)
        #pragma unroll
        for (int j = 0; j < 4; j++)
            wmma::store_matrix_sync(Hs + (m0 + i * 16) * 136 + n0 + j * 16,
                                    acc2[i][j], 136, wmma::mem_row_major);
    __syncthreads();
    for (int idx = tid; idx < 16384; idx += 256) {
        int r = idx >> 7, c = idx & 127;
        float v = Hs[r * 136 + c] + b2s[c];
        out_e[(size_t)(e0 + r) * DD + c] = v;
        atomicAdd(&g_agg[(size_t)srecv[r] * DD + c], v);
    }
}

// ---------------- node MLP kernel ----------------
__global__ __launch_bounds__(256, 1)
void node_wmma_kernel(const float* __restrict__ x,
                      const float* __restrict__ W1, const float* __restrict__ b1,
                      const float* __restrict__ W2, const float* __restrict__ b2,
                      float* __restrict__ out_n)
{
    extern __shared__ float sm[];
    float* As[2] = { sm + OFF_AS0, sm + OFF_AS1 };
    float* Ws[2] = { sm + OFF_WS0, sm + OFF_WS1 };
    float* Hs    = sm + OFF_HS;
    float* b1s   = sm + OFF_B1;
    float* b2s   = sm + OFF_B2;

    const int tid = threadIdx.x;
    const int w   = tid >> 5;
    const int m0  = (w >> 1) * 32;
    const int n0  = (w & 1) * 64;
    const int nb0 = blockIdx.x * 128;

    for (int i = tid; i < 512; i += 256) b1s[i] = b1[i];
    if (tid < 128) b2s[tid] = b2[tid];
    __syncthreads();

    auto loadA = [&](int buf, int kc) {
        const int koff = (kc & 3) * 32;
        #pragma unroll
        for (int i = tid; i < 1024; i += 256) {
            int row = i >> 3, seg = i & 7;
            int nr = min(nb0 + row, NN - 1);
            const float* src = (kc < 4) ? (x + (size_t)nr * DD + koff)
                                        : (g_agg + (size_t)nr * DD + koff);
            cpa16(As[buf] + row * 40 + seg * 4, src + seg * 4);
        }
    };
    auto loadW1 = [&](int buf, int kc, int nc) {
        #pragma unroll
        for (int i = tid; i < 1024; i += 256) {
            int row = i >> 5, seg = i & 31;
            cpa16(Ws[buf] + row * 136 + seg * 4,
                  W1 + (size_t)(kc * 32 + row) * HH + nc * 128 + seg * 4);
        }
    };
    auto loadW2 = [&](int buf, int kc, int nc) {
        #pragma unroll
        for (int i = tid; i < 1024; i += 256) {
            int row = i >> 5, seg = i & 31;
            cpa16(Ws[buf] + row * 136 + seg * 4,
                  W2 + (size_t)(nc * 128 + kc * 32 + row) * DD + seg * 4);
        }
    };

    FragC acc2[2][4];
    #pragma unroll
    for (int i = 0; i < 2; i++)
        #pragma unroll
        for (int j = 0; j < 4; j++) wmma::fill_fragment(acc2[i][j], 0.0f);

    for (int nc = 0; nc < 4; nc++) {
        FragC acc1[2][4];
        #pragma unroll
        for (int i = 0; i < 2; i++)
            #pragma unroll
            for (int j = 0; j < 4; j++) wmma::fill_fragment(acc1[i][j], 0.0f);

        // GEMM1: K = 256 (8 chunks)
        loadA(0, 0); loadW1(0, 0, nc); cp_commit();
        for (int kc = 0; kc < 8; kc++) {
            int cur = kc & 1;
            if (kc < 7) {
                loadA(cur ^ 1, kc + 1); loadW1(cur ^ 1, kc + 1, nc); cp_commit();
                cp_wait<1>();
            } else {
                cp_wait<0>();
            }
            __syncthreads();
            mma_tile(As[cur], 40, Ws[cur], 136, acc1, m0, n0);
            __syncthreads();
        }

        #pragma unroll
        for (int i = 0; i < 2; i++)
            #pragma unroll
            for (int j = 0; j < 4; j++)
                wmma::store_matrix_sync(Hs + (m0 + i * 16) * 136 + n0 + j * 16,
                                        acc1[i][j], 136, wmma::mem_row_major);
        __syncthreads();
        for (int idx = tid; idx < 16384; idx += 256) {
            int r = idx >> 7, c = idx & 127;
            float v = Hs[r * 136 + c] + b1s[nc * 128 + c];
            Hs[r * 136 + c] = v > 0.0f ? v : 0.0f;
        }
        __syncthreads();

        loadW2(0, 0, nc); cp_commit();
        for (int kc = 0; kc < 4; kc++) {
            int cur = kc & 1;
            if (kc < 3) {
                loadW2(cur ^ 1, kc + 1, nc); cp_commit();
                cp_wait<1>();
            } else {
                cp_wait<0>();
            }
            __syncthreads();
            mma_tile(Hs + kc * 32, 136, Ws[cur], 136, acc2, m0, n0);
            __syncthreads();
        }
    }

    #pragma unroll
    for (int i = 0; i < 2; i++)
        #pragma unroll
        for (int j = 0; j < 4; j++)
            wmma::store_matrix_sync(Hs + (m0 + i * 16) * 136 + n0 + j * 16,
                                    acc2[i][j], 136, wmma::mem_row_major);
    __syncthreads();
    for (int idx = tid; idx < 16384; idx += 256) {
        int r = idx >> 7, c = idx & 127;
        int n = nb0 + r;
        if (n < NN)
            out_n[(size_t)n * DD + c] = Hs[r * 136 + c] + b2s[c];
    }
}

// ---------------- launch ----------------
extern "C" void kernel_launch(void* const* d_in, const int* in_sizes, int n_in,
                              void* d_out, int out_size)
{
    const float* x   = (const float*)d_in[0];
    const int*   ei  = (const int*)d_in[1];
    const float* ea  = (const float*)d_in[2];
    const float* We1 = (const float*)d_in[3];
    const float* be1 = (const float*)d_in[4];
    const float* We2 = (const float*)d_in[5];
    const float* be2 = (const float*)d_in[6];
    const float* Wn1 = (const float*)d_in[7];
    const float* bn1 = (const float*)d_in[8];
    const float* Wn2 = (const float*)d_in[9];
    const float* bn2 = (const float*)d_in[10];

    float* out_nodes = (float*)d_out;
    float* out_edges = out_nodes + (size_t)NN * DD;

    cudaFuncSetAttribute(edge_wmma_kernel, cudaFuncAttributeMaxDynamicSharedMemorySize, SMEM_BYTES);
    cudaFuncSetAttribute(node_wmma_kernel, cudaFuncAttributeMaxDynamicSharedMemorySize, SMEM_BYTES);

    zero_agg_kernel<<<(NN * DD + 255) / 256, 256>>>();
    edge_wmma_kernel<<<NE / 128, 256, SMEM_BYTES>>>(x, ei, ea, We1, be1, We2, be2, out_edges);
    node_wmma_kernel<<<(NN + 127) / 128, 256, SMEM_BYTES>>>(x, Wn1, bn1, Wn2, bn2, out_nodes);
}

// round 6
// speedup vs baseline: 2.2832x; 1.5808x over previous
#include <cuda_runtime.h>
#include <mma.h>
#include <cstdint>

using namespace nvcuda;

#define NN 10000
#define NE 320000
#define DD 128
#define HH 512

#define NX  (NN * DD)      // 1,280,000
#define NEA (NE * DD)      // 40,960,000

// ---------------- static device scratch (bss, no runtime allocs) ----------------
__device__ float g_agg[NX];            // fp32 accumulated messages (atomics), then tf32-rounded in place
__device__ float g_x32[NX];            // tf32-rounded x
__device__ float g_ea32[NEA];          // tf32-rounded edge_attr
__device__ float g_W1[384 * 512];      // tf32-rounded We1
__device__ float g_W2[512 * 128];      // tf32-rounded We2
__device__ float g_Wn1[256 * 512];     // tf32-rounded Wn1
__device__ float g_Wn2[512 * 128];     // tf32-rounded Wn2

// ---------------- helpers ----------------
__device__ __forceinline__ float tf32r(float v) {
    float o;
    asm("cvt.rna.tf32.f32 %0, %1;" : "=f"(o) : "f"(v));
    return o;
}
__device__ __forceinline__ uint32_t smem_u32(const void* p) {
    uint32_t a;
    asm("{ .reg .u64 t; cvta.to.shared.u64 t, %1; cvt.u32.u64 %0, t; }" : "=r"(a) : "l"(p));
    return a;
}
__device__ __forceinline__ void cpa16(float* s, const float* g) {
    asm volatile("cp.async.cg.shared.global [%0], [%1], 16;"
                 :: "r"(smem_u32(s)), "l"(g) : "memory");
}
__device__ __forceinline__ void cp_commit() {
    asm volatile("cp.async.commit_group;" ::: "memory");
}
template<int N> __device__ __forceinline__ void cp_wait() {
    asm volatile("cp.async.wait_group %0;" :: "n"(N) : "memory");
}

using FragA = wmma::fragment<wmma::matrix_a, 16, 16, 8, wmma::precision::tf32, wmma::row_major>;
using FragB = wmma::fragment<wmma::matrix_b, 16, 16, 8, wmma::precision::tf32, wmma::row_major>;
using FragC = wmma::fragment<wmma::accumulator, 16, 16, 8, float>;

// acc[2][4] (warp tile 32x64) += A[128xKC] @ B[KCx128], KC = 64, data pre-rounded to tf32
__device__ __forceinline__ void mma_chunk64(const float* __restrict__ A, int lda,
                                            const float* __restrict__ B, int ldb,
                                            FragC (&acc)[2][4], int m0, int n0)
{
    #pragma unroll
    for (int s = 0; s < 8; s++) {
        FragA af[2];
        FragB bf[4];
        #pragma unroll
        for (int i = 0; i < 2; i++)
            wmma::load_matrix_sync(af[i], A + (m0 + i * 16) * lda + s * 8, lda);
        #pragma unroll
        for (int j = 0; j < 4; j++)
            wmma::load_matrix_sync(bf[j], B + (s * 8) * ldb + n0 + j * 16, ldb);
        #pragma unroll
        for (int i = 0; i < 2; i++)
            #pragma unroll
            for (int j = 0; j < 4; j++)
                wmma::mma_sync(acc[i][j], af[i], bf[j], acc[i][j]);
    }
}

// ---------------- prep: round inputs/weights to tf32 copies ----------------
__global__ void prep_kernel(const float* __restrict__ x, const float* __restrict__ ea,
                            const float* __restrict__ We1, const float* __restrict__ We2,
                            const float* __restrict__ Wn1, const float* __restrict__ Wn2)
{
    const int total = NX + NEA + 196608 + 65536 + 131072 + 65536;
    for (int i = blockIdx.x * blockDim.x + threadIdx.x; i < total; i += gridDim.x * blockDim.x) {
        int k = i;
        if (k < NX)            { g_x32[k]  = tf32r(x[k]);   continue; }
        k -= NX;
        if (k < NEA)           { g_ea32[k] = tf32r(ea[k]);  continue; }
        k -= NEA;
        if (k < 196608)        { g_W1[k]   = tf32r(We1[k]); continue; }
        k -= 196608;
        if (k < 65536)         { g_W2[k]   = tf32r(We2[k]); continue; }
        k -= 65536;
        if (k < 131072)        { g_Wn1[k]  = tf32r(Wn1[k]); continue; }
        k -= 131072;
        g_Wn2[k] = tf32r(Wn2[k]);
    }
}

// round g_agg in place (between edge and node kernels)
__global__ void cvt_agg_kernel() {
    for (int i = blockIdx.x * blockDim.x + threadIdx.x; i < NX; i += gridDim.x * blockDim.x)
        g_agg[i] = tf32r(g_agg[i]);
}

// ---------------- smem layout (floats) ----------------
// As: 2 x [128][72]  @ 0       (2 x 9216)
// Ws: 2 x [64][136]  @ 18432   (2 x 8704)
// Hs: [128][136]     @ 35840   (17408)
// b1s [512] @ 53248, b2s [128] @ 53760, idx [256] int @ 53888
#define OFF_AS0 0
#define OFF_AS1 9216
#define OFF_WS0 18432
#define OFF_WS1 27136
#define OFF_HS  35840
#define OFF_B1  53248
#define OFF_B2  53760
#define OFF_IDX 53888
#define SMEM_FLOATS 54144
#define SMEM_BYTES (SMEM_FLOATS * 4)   // 216,576

// ---------------- edge MLP kernel ----------------
__global__ __launch_bounds__(256, 1)
void edge_wmma_kernel(const int* __restrict__ eidx,
                      const float* __restrict__ b1, const float* __restrict__ b2,
                      float* __restrict__ out_e)
{
    extern __shared__ float sm[];
    float* As[2] = { sm + OFF_AS0, sm + OFF_AS1 };
    float* Ws[2] = { sm + OFF_WS0, sm + OFF_WS1 };
    float* Hs    = sm + OFF_HS;
    float* b1s   = sm + OFF_B1;
    float* b2s   = sm + OFF_B2;
    int*   ssend = (int*)(sm + OFF_IDX);
    int*   srecv = ssend + 128;

    const int tid = threadIdx.x;
    const int w   = tid >> 5;
    const int m0  = (w >> 1) * 32;   // 4 m-warps
    const int n0  = (w & 1) * 64;    // 2 n-warps
    const int e0  = blockIdx.x * 128;

    if (tid < 128) {
        int s = eidx[e0 + tid];
        ssend[tid] = min(max(s, 0), NN - 1);
    } else {
        int r = eidx[NE + e0 + tid - 128];
        srecv[tid - 128] = min(max(r, 0), NN - 1);
    }
    for (int i = tid; i < 512; i += 256) b1s[i] = b1[i];
    if (tid < 128) b2s[tid] = b2[tid];
    __syncthreads();

    // A chunk kc in [0,6): cols kc*64..+64 of [x[s] | x[r] | ea]
    auto loadA = [&](int buf, int kc) {
        const int koff = (kc & 1) * 64;
        #pragma unroll
        for (int i = tid; i < 2048; i += 256) {
            int row = i >> 4, seg = i & 15;
            const float* src;
            if (kc < 2)      src = g_x32  + (size_t)ssend[row] * DD + koff;
            else if (kc < 4) src = g_x32  + (size_t)srecv[row] * DD + koff;
            else             src = g_ea32 + (size_t)(e0 + row) * DD + koff;
            cpa16(As[buf] + row * 72 + seg * 4, src + seg * 4);
        }
    };
    auto loadW1 = [&](int buf, int kc, int nc) {
        #pragma unroll
        for (int i = tid; i < 2048; i += 256) {
            int row = i >> 5, seg = i & 31;
            cpa16(Ws[buf] + row * 136 + seg * 4,
                  g_W1 + (size_t)(kc * 64 + row) * HH + nc * 128 + seg * 4);
        }
    };
    auto loadW2 = [&](int buf, int kc, int nc) {
        #pragma unroll
        for (int i = tid; i < 2048; i += 256) {
            int row = i >> 5, seg = i & 31;
            cpa16(Ws[buf] + row * 136 + seg * 4,
                  g_W2 + (size_t)(nc * 128 + kc * 64 + row) * DD + seg * 4);
        }
    };

    FragC acc2[2][4];
    #pragma unroll
    for (int i = 0; i < 2; i++)
        #pragma unroll
        for (int j = 0; j < 4; j++) wmma::fill_fragment(acc2[i][j], 0.0f);

    for (int nc = 0; nc < 4; nc++) {
        FragC acc1[2][4];
        #pragma unroll
        for (int i = 0; i < 2; i++)
            #pragma unroll
            for (int j = 0; j < 4; j++) wmma::fill_fragment(acc1[i][j], 0.0f);

        // ---- GEMM1: K = 384 -> 6 chunks of 64, double-buffered ----
        loadA(0, 0); loadW1(0, 0, nc); cp_commit();
        for (int kc = 0; kc < 6; kc++) {
            int cur = kc & 1;
            if (kc < 5) { loadA(cur ^ 1, kc + 1); loadW1(cur ^ 1, kc + 1, nc); cp_commit(); cp_wait<1>(); }
            else        { cp_wait<0>(); }
            __syncthreads();
            mma_chunk64(As[cur], 72, Ws[cur], 136, acc1, m0, n0);
            __syncthreads();
        }

        // ---- acc1 -> Hs with bias + relu + tf32 round ----
        #pragma unroll
        for (int i = 0; i < 2; i++)
            #pragma unroll
            for (int j = 0; j < 4; j++)
                wmma::store_matrix_sync(Hs + (m0 + i * 16) * 136 + n0 + j * 16,
                                        acc1[i][j], 136, wmma::mem_row_major);
        __syncthreads();
        for (int idx = tid; idx < 16384; idx += 256) {
            int r = idx >> 7, c = idx & 127;
            float v = Hs[r * 136 + c] + b1s[nc * 128 + c];
            Hs[r * 136 + c] = tf32r(v > 0.0f ? v : 0.0f);
        }
        __syncthreads();

        // ---- GEMM2: K = 128 -> 2 chunks of 64, A = Hs resident ----
        loadW2(0, 0, nc); cp_commit();
        for (int kc = 0; kc < 2; kc++) {
            int cur = kc & 1;
            if (kc < 1) { loadW2(cur ^ 1, 1, nc); cp_commit(); cp_wait<1>(); }
            else        { cp_wait<0>(); }
            __syncthreads();
            mma_chunk64(Hs + kc * 64, 136, Ws[cur], 136, acc2, m0, n0);
            __syncthreads();
        }
    }

    // ---- epilogue: acc2 -> Hs, + b2, write out + scatter atomics ----
    #pragma unroll
    for (int i = 0; i < 2; i++)
        #pragma unroll
        for (int j = 0; j < 4; j++)
            wmma::store_matrix_sync(Hs + (m0 + i * 16) * 136 + n0 + j * 16,
                                    acc2[i][j], 136, wmma::mem_row_major);
    __syncthreads();
    for (int idx = tid; idx < 16384; idx += 256) {
        int r = idx >> 7, c = idx & 127;
        float v = Hs[r * 136 + c] + b2s[c];
        out_e[(size_t)(e0 + r) * DD + c] = v;
        atomicAdd(&g_agg[(size_t)srecv[r] * DD + c], v);
    }
}

// ---------------- node MLP kernel (self-cleans g_agg) ----------------
__global__ __launch_bounds__(256, 1)
void node_wmma_kernel(const float* __restrict__ b1, const float* __restrict__ b2,
                      float* __restrict__ out_n)
{
    extern __shared__ float sm[];
    float* As[2] = { sm + OFF_AS0, sm + OFF_AS1 };
    float* Ws[2] = { sm + OFF_WS0, sm + OFF_WS1 };
    float* Hs    = sm + OFF_HS;
    float* b1s   = sm + OFF_B1;
    float* b2s   = sm + OFF_B2;

    const int tid = threadIdx.x;
    const int w   = tid >> 5;
    const int m0  = (w >> 1) * 32;
    const int n0  = (w & 1) * 64;
    const int nb0 = blockIdx.x * 128;

    for (int i = tid; i < 512; i += 256) b1s[i] = b1[i];
    if (tid < 128) b2s[tid] = b2[tid];
    __syncthreads();

    auto loadA = [&](int buf, int kc) {
        const int koff = (kc & 1) * 64;
        #pragma unroll
        for (int i = tid; i < 2048; i += 256) {
            int row = i >> 4, seg = i & 15;
            int nr = min(nb0 + row, NN - 1);
            const float* src = (kc < 2) ? (g_x32 + (size_t)nr * DD + koff)
                                        : (g_agg + (size_t)nr * DD + koff);
            cpa16(As[buf] + row * 72 + seg * 4, src + seg * 4);
        }
    };
    auto loadW1 = [&](int buf, int kc, int nc) {
        #pragma unroll
        for (int i = tid; i < 2048; i += 256) {
            int row = i >> 5, seg = i & 31;
            cpa16(Ws[buf] + row * 136 + seg * 4,
                  g_Wn1 + (size_t)(kc * 64 + row) * HH + nc * 128 + seg * 4);
        }
    };
    auto loadW2 = [&](int buf, int kc, int nc) {
        #pragma unroll
        for (int i = tid; i < 2048; i += 256) {
            int row = i >> 5, seg = i & 31;
            cpa16(Ws[buf] + row * 136 + seg * 4,
                  g_Wn2 + (size_t)(nc * 128 + kc * 64 + row) * DD + seg * 4);
        }
    };

    FragC acc2[2][4];
    #pragma unroll
    for (int i = 0; i < 2; i++)
        #pragma unroll
        for (int j = 0; j < 4; j++) wmma::fill_fragment(acc2[i][j], 0.0f);

    for (int nc = 0; nc < 4; nc++) {
        FragC acc1[2][4];
        #pragma unroll
        for (int i = 0; i < 2; i++)
            #pragma unroll
            for (int j = 0; j < 4; j++) wmma::fill_fragment(acc1[i][j], 0.0f);

        // GEMM1: K = 256 -> 4 chunks of 64
        loadA(0, 0); loadW1(0, 0, nc); cp_commit();
        for (int kc = 0; kc < 4; kc++) {
            int cur = kc & 1;
            if (kc < 3) { loadA(cur ^ 1, kc + 1); loadW1(cur ^ 1, kc + 1, nc); cp_commit(); cp_wait<1>(); }
            else        { cp_wait<0>(); }
            __syncthreads();
            mma_chunk64(As[cur], 72, Ws[cur], 136, acc1, m0, n0);
            __syncthreads();
        }

        #pragma unroll
        for (int i = 0; i < 2; i++)
            #pragma unroll
            for (int j = 0; j < 4; j++)
                wmma::store_matrix_sync(Hs + (m0 + i * 16) * 136 + n0 + j * 16,
                                        acc1[i][j], 136, wmma::mem_row_major);
        __syncthreads();
        for (int idx = tid; idx < 16384; idx += 256) {
            int r = idx >> 7, c = idx & 127;
            float v = Hs[r * 136 + c] + b1s[nc * 128 + c];
            Hs[r * 136 + c] = tf32r(v > 0.0f ? v : 0.0f);
        }
        __syncthreads();

        loadW2(0, 0, nc); cp_commit();
        for (int kc = 0; kc < 2; kc++) {
            int cur = kc & 1;
            if (kc < 1) { loadW2(cur ^ 1, 1, nc); cp_commit(); cp_wait<1>(); }
            else        { cp_wait<0>(); }
            __syncthreads();
            mma_chunk64(Hs + kc * 64, 136, Ws[cur], 136, acc2, m0, n0);
            __syncthreads();
        }
    }

    #pragma unroll
    for (int i = 0; i < 2; i++)
        #pragma unroll
        for (int j = 0; j < 4; j++)
            wmma::store_matrix_sync(Hs + (m0 + i * 16) * 136 + n0 + j * 16,
                                    acc2[i][j], 136, wmma::mem_row_major);
    __syncthreads();
    for (int idx = tid; idx < 16384; idx += 256) {
        int r = idx >> 7, c = idx & 127;
        int n = nb0 + r;
        if (n < NN) {
            out_n[(size_t)n * DD + c] = Hs[r * 136 + c] + b2s[c];
            g_agg[(size_t)n * DD + c] = 0.0f;   // self-clean for next call / replay
        }
    }
}

// ---------------- launch ----------------
extern "C" void kernel_launch(void* const* d_in, const int* in_sizes, int n_in,
                              void* d_out, int out_size)
{
    const float* x   = (const float*)d_in[0];
    const int*   ei  = (const int*)d_in[1];
    const float* ea  = (const float*)d_in[2];
    const float* We1 = (const float*)d_in[3];
    const float* be1 = (const float*)d_in[4];
    const float* We2 = (const float*)d_in[5];
    const float* be2 = (const float*)d_in[6];
    const float* Wn1 = (const float*)d_in[7];
    const float* bn1 = (const float*)d_in[8];
    const float* Wn2 = (const float*)d_in[9];
    const float* bn2 = (const float*)d_in[10];

    float* out_nodes = (float*)d_out;
    float* out_edges = out_nodes + (size_t)NN * DD;

    cudaFuncSetAttribute(edge_wmma_kernel, cudaFuncAttributeMaxDynamicSharedMemorySize, SMEM_BYTES);
    cudaFuncSetAttribute(node_wmma_kernel, cudaFuncAttributeMaxDynamicSharedMemorySize, SMEM_BYTES);

    prep_kernel<<<4096, 256>>>(x, ea, We1, We2, Wn1, Wn2);
    edge_wmma_kernel<<<NE / 128, 256, SMEM_BYTES>>>(ei, be1, be2, out_edges);
    cvt_agg_kernel<<<1280, 256>>>();
    node_wmma_kernel<<<(NN + 127) / 128, 256, SMEM_BYTES>>>(bn1, bn2, out_nodes);
}

// round 9
// speedup vs baseline: 2.5998x; 1.1387x over previous
#include <cuda_runtime.h>
#include <mma.h>
#include <cstdint>

using namespace nvcuda;

#define NN 10000
#define NE 320000
#define DD 128
#define HH 512

#define NX  (NN * DD)
#define NEA (NE * DD)

// ---------------- static device scratch (bss, allocated at module load) ----------------
__device__ float g_agg[NX];
__device__ float g_x32[NX];
__device__ float g_ea32[NEA];
__device__ float g_W1[384 * 512];
__device__ float g_W2[512 * 128];
__device__ float g_Wn1[256 * 512];
__device__ float g_Wn2[512 * 128];
__device__ float g_H[(size_t)NE * HH];   // 655MB hidden-activation scratch (reused by node pass)

// ---------------- helpers ----------------
__device__ __forceinline__ float tf32r(float v) {
    float o;
    asm("cvt.rna.tf32.f32 %0, %1;" : "=f"(o) : "f"(v));
    return o;
}
__device__ __forceinline__ uint32_t smem_u32(const void* p) {
    uint32_t a;
    asm("{ .reg .u64 t; cvta.to.shared.u64 t, %1; cvt.u32.u64 %0, t; }" : "=r"(a) : "l"(p));
    return a;
}
__device__ __forceinline__ void cpa16(float* s, const float* g) {
    asm volatile("cp.async.cg.shared.global [%0], [%1], 16;"
                 :: "r"(smem_u32(s)), "l"(g) : "memory");
}
__device__ __forceinline__ void cp_commit() {
    asm volatile("cp.async.commit_group;" ::: "memory");
}
template<int N> __device__ __forceinline__ void cp_wait() {
    asm volatile("cp.async.wait_group %0;" :: "n"(N) : "memory");
}

using FragA = wmma::fragment<wmma::matrix_a, 16, 16, 8, wmma::precision::tf32, wmma::row_major>;
using FragB = wmma::fragment<wmma::matrix_b, 16, 16, 8, wmma::precision::tf32, wmma::row_major>;
using FragC = wmma::fragment<wmma::accumulator, 16, 16, 8, float>;

#define LDA 36    // A row stride (32 + 4 pad) — conflict-free fragment loads
#define LDB 132   // B row stride (128 + 4 pad)

// acc[2][4] (warp 32x64) += A[128x32] @ B[32x128]; data pre-rounded to tf32
__device__ __forceinline__ void mma_chunk32(const float* __restrict__ A,
                                            const float* __restrict__ B,
                                            FragC (&acc)[2][4], int m0, int n0)
{
    #pragma unroll
    for (int s = 0; s < 4; s++) {
        FragA af[2];
        FragB bf[4];
        #pragma unroll
        for (int i = 0; i < 2; i++)
            wmma::load_matrix_sync(af[i], A + (m0 + i * 16) * LDA + s * 8, LDA);
        #pragma unroll
        for (int j = 0; j < 4; j++)
            wmma::load_matrix_sync(bf[j], B + (s * 8) * LDB + n0 + j * 16, LDB);
        #pragma unroll
        for (int i = 0; i < 2; i++)
            #pragma unroll
            for (int j = 0; j < 4; j++)
                wmma::mma_sync(acc[i][j], af[i], bf[j], acc[i][j]);
    }
}

// ---------------- smem layout (floats) ----------------
#define OFF_AS0 0
#define OFF_AS1 4608
#define OFF_WS0 9216
#define OFF_WS1 13440
#define OFF_B   17664
#define OFF_IDX 17792
#define SMEM_FLOATS 18048
#define SMEM_BYTES (SMEM_FLOATS * 4)   // 72,192 -> 2+ CTAs/SM

// ---------------- prep: round inputs/weights to tf32 copies ----------------
__global__ void prep_kernel(const float* __restrict__ x, const float* __restrict__ ea,
                            const float* __restrict__ We1, const float* __restrict__ We2,
                            const float* __restrict__ Wn1, const float* __restrict__ Wn2)
{
    const int total = NX + NEA + 196608 + 65536 + 131072 + 65536;
    for (int i = blockIdx.x * blockDim.x + threadIdx.x; i < total; i += gridDim.x * blockDim.x) {
        int k = i;
        if (k < NX)     { g_x32[k]  = tf32r(x[k]);   continue; }
        k -= NX;
        if (k < NEA)    { g_ea32[k] = tf32r(ea[k]);  continue; }
        k -= NEA;
        if (k < 196608) { g_W1[k]   = tf32r(We1[k]); continue; }
        k -= 196608;
        if (k < 65536)  { g_W2[k]   = tf32r(We2[k]); continue; }
        k -= 65536;
        if (k < 131072) { g_Wn1[k]  = tf32r(Wn1[k]); continue; }
        k -= 131072;
        g_Wn2[k] = tf32r(Wn2[k]);
    }
}

__global__ void cvt_agg_kernel() {
    for (int i = blockIdx.x * blockDim.x + threadIdx.x; i < NX; i += gridDim.x * blockDim.x)
        g_agg[i] = tf32r(g_agg[i]);
}

// =====================================================================
// E1: H[e, nc*128 .. +128] = tf32(relu(gather(e) @ W1[:, block] + b1))
// grid (2500, 4)
// =====================================================================
__global__ __launch_bounds__(256, 2)
void e1_kernel(const int* __restrict__ eidx, const float* __restrict__ b1)
{
    extern __shared__ float sm[];
    float* As[2] = { sm + OFF_AS0, sm + OFF_AS1 };
    float* Ws[2] = { sm + OFF_WS0, sm + OFF_WS1 };
    float* bs    = sm + OFF_B;
    int*   ssend = (int*)(sm + OFF_IDX);
    int*   srecv = ssend + 128;

    const int tid = threadIdx.x;
    const int w = tid >> 5;
    const int m0 = (w >> 1) * 32, n0 = (w & 1) * 64;
    const int e0 = blockIdx.x * 128;
    const int nc = blockIdx.y;

    if (tid < 128) {
        int s = eidx[e0 + tid];
        ssend[tid] = min(max(s, 0), NN - 1);
    } else if (tid < 256) {
        int r = eidx[NE + e0 + tid - 128];
        srecv[tid - 128] = min(max(r, 0), NN - 1);
    }
    if (tid < 128) bs[tid] = b1[nc * 128 + tid];
    __syncthreads();

    auto loadA = [&](int buf, int kc) {
        const int koff = (kc & 3) * 32;
        #pragma unroll
        for (int i = tid; i < 1024; i += 256) {
            int row = i >> 3, seg = i & 7;
            const float* src;
            if (kc < 4)      src = g_x32  + (size_t)ssend[row] * DD + koff;
            else if (kc < 8) src = g_x32  + (size_t)srecv[row] * DD + koff;
            else             src = g_ea32 + (size_t)(e0 + row) * DD + koff;
            cpa16(As[buf] + row * LDA + seg * 4, src + seg * 4);
        }
    };
    auto loadW = [&](int buf, int kc) {
        #pragma unroll
        for (int i = tid; i < 1024; i += 256) {
            int row = i >> 5, seg = i & 31;
            cpa16(Ws[buf] + row * LDB + seg * 4,
                  g_W1 + (size_t)(kc * 32 + row) * HH + nc * 128 + seg * 4);
        }
    };

    FragC acc[2][4];
    #pragma unroll
    for (int i = 0; i < 2; i++)
        #pragma unroll
        for (int j = 0; j < 4; j++) wmma::fill_fragment(acc[i][j], 0.0f);

    loadA(0, 0); loadW(0, 0); cp_commit();
    for (int kc = 0; kc < 12; kc++) {
        int cur = kc & 1;
        if (kc < 11) { loadA(cur ^ 1, kc + 1); loadW(cur ^ 1, kc + 1); cp_commit(); cp_wait<1>(); }
        else         { cp_wait<0>(); }
        __syncthreads();
        mma_chunk32(As[cur], Ws[cur], acc, m0, n0);
        __syncthreads();
    }

    // epilogue: acc -> smem overlay -> bias+relu+round -> g_H
    float* Cs = sm;  // reuse As/Ws region (128 x LDB)
    #pragma unroll
    for (int i = 0; i < 2; i++)
        #pragma unroll
        for (int j = 0; j < 4; j++)
            wmma::store_matrix_sync(Cs + (m0 + i * 16) * LDB + n0 + j * 16,
                                    acc[i][j], LDB, wmma::mem_row_major);
    __syncthreads();
    for (int idx = tid; idx < 16384; idx += 256) {
        int r = idx >> 7, c = idx & 127;
        float v = Cs[r * LDB + c] + bs[c];
        g_H[(size_t)(e0 + r) * HH + nc * 128 + c] = tf32r(v > 0.0f ? v : 0.0f);
    }
}

// =====================================================================
// E2: out_e = H @ W2 + b2;  atomic scatter into g_agg[recv]
// grid 2500
// =====================================================================
__global__ __launch_bounds__(256, 2)
void e2_kernel(const int* __restrict__ eidx, const float* __restrict__ b2,
               float* __restrict__ out_e)
{
    extern __shared__ float sm[];
    float* As[2] = { sm + OFF_AS0, sm + OFF_AS1 };
    float* Ws[2] = { sm + OFF_WS0, sm + OFF_WS1 };
    float* bs    = sm + OFF_B;
    int*   srecv = (int*)(sm + OFF_IDX);

    const int tid = threadIdx.x;
    const int w = tid >> 5;
    const int m0 = (w >> 1) * 32, n0 = (w & 1) * 64;
    const int e0 = blockIdx.x * 128;

    if (tid < 128) {
        int r = eidx[NE + e0 + tid];
        srecv[tid] = min(max(r, 0), NN - 1);
        bs[tid] = b2[tid];
    }
    __syncthreads();

    auto loadA = [&](int buf, int kc) {
        #pragma unroll
        for (int i = tid; i < 1024; i += 256) {
            int row = i >> 3, seg = i & 7;
            cpa16(As[buf] + row * LDA + seg * 4,
                  g_H + (size_t)(e0 + row) * HH + kc * 32 + seg * 4);
        }
    };
    auto loadW = [&](int buf, int kc) {
        #pragma unroll
        for (int i = tid; i < 1024; i += 256) {
            int row = i >> 5, seg = i & 31;
            cpa16(Ws[buf] + row * LDB + seg * 4,
                  g_W2 + (size_t)(kc * 32 + row) * DD + seg * 4);
        }
    };

    FragC acc[2][4];
    #pragma unroll
    for (int i = 0; i < 2; i++)
        #pragma unroll
        for (int j = 0; j < 4; j++) wmma::fill_fragment(acc[i][j], 0.0f);

    loadA(0, 0); loadW(0, 0); cp_commit();
    for (int kc = 0; kc < 16; kc++) {
        int cur = kc & 1;
        if (kc < 15) { loadA(cur ^ 1, kc + 1); loadW(cur ^ 1, kc + 1); cp_commit(); cp_wait<1>(); }
        else         { cp_wait<0>(); }
        __syncthreads();
        mma_chunk32(As[cur], Ws[cur], acc, m0, n0);
        __syncthreads();
    }

    float* Cs = sm;
    #pragma unroll
    for (int i = 0; i < 2; i++)
        #pragma unroll
        for (int j = 0; j < 4; j++)
            wmma::store_matrix_sync(Cs + (m0 + i * 16) * LDB + n0 + j * 16,
                                    acc[i][j], LDB, wmma::mem_row_major);
    __syncthreads();
    for (int idx = tid; idx < 16384; idx += 256) {
        int r = idx >> 7, c = idx & 127;
        float v = Cs[r * LDB + c] + bs[c];
        out_e[(size_t)(e0 + r) * DD + c] = v;
        atomicAdd(&g_agg[(size_t)srecv[r] * DD + c], v);
    }
}

// =====================================================================
// N1: H[n, nc*128 .. +128] = tf32(relu([x|agg] @ Wn1[:, block] + bn1))
// grid (79, 4)
// =====================================================================
__global__ __launch_bounds__(256, 2)
void n1_kernel(const float* __restrict__ b1)
{
    extern __shared__ float sm[];
    float* As[2] = { sm + OFF_AS0, sm + OFF_AS1 };
    float* Ws[2] = { sm + OFF_WS0, sm + OFF_WS1 };
    float* bs    = sm + OFF_B;

    const int tid = threadIdx.x;
    const int w = tid >> 5;
    const int m0 = (w >> 1) * 32, n0 = (w & 1) * 64;
    const int nb0 = blockIdx.x * 128;
    const int nc = blockIdx.y;

    if (tid < 128) bs[tid] = b1[nc * 128 + tid];
    __syncthreads();

    auto loadA = [&](int buf, int kc) {
        const int koff = (kc & 3) * 32;
        #pragma unroll
        for (int i = tid; i < 1024; i += 256) {
            int row = i >> 3, seg = i & 7;
            int nr = min(nb0 + row, NN - 1);
            const float* src = (kc < 4) ? (g_x32 + (size_t)nr * DD + koff)
                                        : (g_agg + (size_t)nr * DD + koff);
            cpa16(As[buf] + row * LDA + seg * 4, src + seg * 4);
        }
    };
    auto loadW = [&](int buf, int kc) {
        #pragma unroll
        for (int i = tid; i < 1024; i += 256) {
            int row = i >> 5, seg = i & 31;
            cpa16(Ws[buf] + row * LDB + seg * 4,
                  g_Wn1 + (size_t)(kc * 32 + row) * HH + nc * 128 + seg * 4);
        }
    };

    FragC acc[2][4];
    #pragma unroll
    for (int i = 0; i < 2; i++)
        #pragma unroll
        for (int j = 0; j < 4; j++) wmma::fill_fragment(acc[i][j], 0.0f);

    loadA(0, 0); loadW(0, 0); cp_commit();
    for (int kc = 0; kc < 8; kc++) {
        int cur = kc & 1;
        if (kc < 7) { loadA(cur ^ 1, kc + 1); loadW(cur ^ 1, kc + 1); cp_commit(); cp_wait<1>(); }
        else        { cp_wait<0>(); }
        __syncthreads();
        mma_chunk32(As[cur], Ws[cur], acc, m0, n0);
        __syncthreads();
    }

    float* Cs = sm;
    #pragma unroll
    for (int i = 0; i < 2; i++)
        #pragma unroll
        for (int j = 0; j < 4; j++)
            wmma::store_matrix_sync(Cs + (m0 + i * 16) * LDB + n0 + j * 16,
                                    acc[i][j], LDB, wmma::mem_row_major);
    __syncthreads();
    for (int idx = tid; idx < 16384; idx += 256) {
        int r = idx >> 7, c = idx & 127;
        int n = nb0 + r;
        if (n < NN) {
            float v = Cs[r * LDB + c] + bs[c];
            g_H[(size_t)n * HH + nc * 128 + c] = tf32r(v > 0.0f ? v : 0.0f);
        }
    }
}

// =====================================================================
// N2: out_n = H @ Wn2 + bn2;  self-cleans g_agg.  grid 79
// =====================================================================
__global__ __launch_bounds__(256, 2)
void n2_kernel(const float* __restrict__ b2, float* __restrict__ out_n)
{
    extern __shared__ float sm[];
    float* As[2] = { sm + OFF_AS0, sm + OFF_AS1 };
    float* Ws[2] = { sm + OFF_WS0, sm + OFF_WS1 };
    float* bs    = sm + OFF_B;

    const int tid = threadIdx.x;
    const int w = tid >> 5;
    const int m0 = (w >> 1) * 32, n0 = (w & 1) * 64;
    const int nb0 = blockIdx.x * 128;

    if (tid < 128) bs[tid] = b2[tid];
    __syncthreads();

    auto loadA = [&](int buf, int kc) {
        #pragma unroll
        for (int i = tid; i < 1024; i += 256) {
            int row = i >> 3, seg = i & 7;
            int nr = min(nb0 + row, NN - 1);
            cpa16(As[buf] + row * LDA + seg * 4,
                  g_H + (size_t)nr * HH + kc * 32 + seg * 4);
        }
    };
    auto loadW = [&](int buf, int kc) {
        #pragma unroll
        for (int i = tid; i < 1024; i += 256) {
            int row = i >> 5, seg = i & 31;
            cpa16(Ws[buf] + row * LDB + seg * 4,
                  g_Wn2 + (size_t)(kc * 32 + row) * DD + seg * 4);
        }
    };

    FragC acc[2][4];
    #pragma unroll
    for (int i = 0; i < 2; i++)
        #pragma unroll
        for (int j = 0; j < 4; j++) wmma::fill_fragment(acc[i][j], 0.0f);

    loadA(0, 0); loadW(0, 0); cp_commit();
    for (int kc = 0; kc < 16; kc++) {
        int cur = kc & 1;
        if (kc < 15) { loadA(cur ^ 1, kc + 1); loadW(cur ^ 1, kc + 1); cp_commit(); cp_wait<1>(); }
        else         { cp_wait<0>(); }
        __syncthreads();
        mma_chunk32(As[cur], Ws[cur], acc, m0, n0);
        __syncthreads();
    }

    float* Cs = sm;
    #pragma unroll
    for (int i = 0; i < 2; i++)
        #pragma unroll
        for (int j = 0; j < 4; j++)
            wmma::store_matrix_sync(Cs + (m0 + i * 16) * LDB + n0 + j * 16,
                                    acc[i][j], LDB, wmma::mem_row_major);
    __syncthreads();
    for (int idx = tid; idx < 16384; idx += 256) {
        int r = idx >> 7, c = idx & 127;
        int n = nb0 + r;
        if (n < NN) {
            out_n[(size_t)n * DD + c] = Cs[r * LDB + c] + bs[c];
            g_agg[(size_t)n * DD + c] = 0.0f;   // self-clean for graph replay
        }
    }
}

// ---------------- launch ----------------
extern "C" void kernel_launch(void* const* d_in, const int* in_sizes, int n_in,
                              void* d_out, int out_size)
{
    const float* x   = (const float*)d_in[0];
    const int*   ei  = (const int*)d_in[1];
    const float* ea  = (const float*)d_in[2];
    const float* We1 = (const float*)d_in[3];
    const float* be1 = (const float*)d_in[4];
    const float* We2 = (const float*)d_in[5];
    const float* be2 = (const float*)d_in[6];
    const float* Wn1 = (const float*)d_in[7];
    const float* bn1 = (const float*)d_in[8];
    const float* Wn2 = (const float*)d_in[9];
    const float* bn2 = (const float*)d_in[10];

    float* out_nodes = (float*)d_out;
    float* out_edges = out_nodes + (size_t)NN * DD;

    cudaFuncSetAttribute(e1_kernel, cudaFuncAttributeMaxDynamicSharedMemorySize, SMEM_BYTES);
    cudaFuncSetAttribute(e2_kernel, cudaFuncAttributeMaxDynamicSharedMemorySize, SMEM_BYTES);
    cudaFuncSetAttribute(n1_kernel, cudaFuncAttributeMaxDynamicSharedMemorySize, SMEM_BYTES);
    cudaFuncSetAttribute(n2_kernel, cudaFuncAttributeMaxDynamicSharedMemorySize, SMEM_BYTES);

    prep_kernel<<<4096, 256>>>(x, ea, We1, We2, Wn1, Wn2);
    e1_kernel<<<dim3(NE / 128, 4), 256, SMEM_BYTES>>>(ei, be1);
    e2_kernel<<<NE / 128, 256, SMEM_BYTES>>>(ei, be2, out_edges);
    cvt_agg_kernel<<<1280, 256>>>();
    n1_kernel<<<dim3((NN + 127) / 128, 4), 256, SMEM_BYTES>>>(bn1);
    n2_kernel<<<(NN + 127) / 128, 256, SMEM_BYTES>>>(bn2, out_nodes);
}